// round 13
// baseline (speedup 1.0000x reference)
#include <cuda_runtime.h>
#include <cuda_fp16.h>
#include <cstdint>

#define ATOMS   128
#define FDIM    512
#define HID     128
#define KC      64
#define NCH     (FDIM / KC)   // 8
#define THREADS 256

#define LDA 72    // halves per A row (64 + 8 pad)
#define LDB 136   // halves per B row (128 + 8 pad)

#define SA_SZ   (ATOMS * LDA * 2)       // 18432
#define SB_SZ   (KC * LDB * 2)          // 17408
#define SA_BASE 0                       // 3 stages (ch % 3)
#define SB_BASE (3 * SA_SZ)             // 55296, 3 stages (ch % 3)
#define B1F     (SB_BASE + 3 * SB_SZ)   // 107520 (128 f32)
#define W2F     (B1F + 512)             // 108032 (128 f32)
#define ZPF     (W2F + 512)             // 108544 (256 f32)
#define GTF     (ZPF + 1024)            // 109568 (128 f32)
#define SMEM_BYTES (GTF + 512)          // 110080  (x2 CTAs = 220160 < 228KB)

__device__ __half g_W1h[FDIM * HID];    // W1 fp16, [k][n]

__global__ void format_w1_kernel(const float* __restrict__ W1) {
    int idx = blockIdx.x * blockDim.x + threadIdx.x;   // 16384 float4 slots
    float4 v = ((const float4*)W1)[idx];
    __half2 a = __floats2half2_rn(v.x, v.y);
    __half2 b = __floats2half2_rn(v.z, v.w);
    ((__half2*)g_W1h)[2 * idx]     = a;
    ((__half2*)g_W1h)[2 * idx + 1] = b;
}

__device__ __forceinline__ uint32_t smem_u32(const void* p) {
    uint32_t a;
    asm("{ .reg .u64 t; cvta.to.shared.u64 t, %1; cvt.u32.u64 %0, t; }" : "=r"(a) : "l"(p));
    return a;
}
__device__ __forceinline__ uint32_t h2_bits(__half2 v) {
    uint32_t u; __builtin_memcpy(&u, &v, 4); return u;
}
__device__ __forceinline__ void cp_async16(uint32_t dst, const void* src) {
    asm volatile("cp.async.cg.shared.global [%0], [%1], 16;\n" :: "r"(dst), "l"(src) : "memory");
}
__device__ __forceinline__ void ldsm_x4(uint32_t (&r)[4], uint32_t addr) {
    asm volatile("ldmatrix.sync.aligned.m8n8.x4.shared.b16 {%0,%1,%2,%3}, [%4];"
                 : "=r"(r[0]), "=r"(r[1]), "=r"(r[2]), "=r"(r[3]) : "r"(addr));
}
__device__ __forceinline__ void ldsm_x4t(uint32_t (&r)[4], uint32_t addr) {
    asm volatile("ldmatrix.sync.aligned.m8n8.x4.trans.shared.b16 {%0,%1,%2,%3}, [%4];"
                 : "=r"(r[0]), "=r"(r[1]), "=r"(r[2]), "=r"(r[3]) : "r"(addr));
}
__device__ __forceinline__ void mma16816(float (&d)[4], const uint32_t (&a)[4],
                                         uint32_t b0, uint32_t b1) {
    asm volatile(
        "mma.sync.aligned.m16n8k16.row.col.f32.f16.f16.f32 "
        "{%0,%1,%2,%3}, {%4,%5,%6,%7}, {%8,%9}, {%0,%1,%2,%3};\n"
        : "+f"(d[0]), "+f"(d[1]), "+f"(d[2]), "+f"(d[3])
        : "r"(a[0]), "r"(a[1]), "r"(a[2]), "r"(a[3]), "r"(b0), "r"(b1));
}

__global__ void __launch_bounds__(THREADS, 2)
atom_pool_kernel(const float* __restrict__ h,
                 const float* __restrict__ b1,
                 const float* __restrict__ W2,
                 const float* __restrict__ b2,
                 float* __restrict__ out) {
    extern __shared__ char smem[];
    const uint32_t sbase = smem_u32(smem);
    float* smf = (float*)smem;

    const int m    = blockIdx.x;
    const int tid  = threadIdx.x;
    const int wid  = tid >> 5;
    const int lane = tid & 31;
    const int g    = lane >> 2;
    const int tg   = lane & 3;

    const float* hm = h + (size_t)m * ATOMS * FDIM;

    if (tid < HID) { smf[B1F / 4 + tid] = b1[tid]; smf[W2F / 4 + tid] = W2[tid]; }

    const int R = (wid & 3) * 32;
    const int C = (wid >> 2) * 64;

    float c[2][8][4];
#pragma unroll
    for (int mt = 0; mt < 2; mt++)
#pragma unroll
        for (int ti = 0; ti < 8; ti++)
#pragma unroll
            for (int j = 0; j < 4; j++) c[mt][ti][j] = 0.f;

#define CPB(ch)                                                                    \
    do {                                                                           \
        uint32_t _dB = sbase + SB_BASE + ((ch) % 3) * SB_SZ;                       \
        const __half* _gB = g_W1h + (size_t)(ch) * KC * HID;                       \
        _Pragma("unroll")                                                          \
        for (int j = 0; j < 4; j++) {                                              \
            int idx = j * THREADS + tid;                                           \
            int r = idx >> 4, s = idx & 15;                                        \
            cp_async16(_dB + (r * LDB + s * 8) * 2, _gB + (size_t)r * HID + s * 8);\
        }                                                                          \
        asm volatile("cp.async.commit_group;\n" ::: "memory");                     \
    } while (0)

#define LDGA(ch)                                                                   \
    do {                                                                           \
        const float* _gA = hm + (ch) * KC;                                         \
        _Pragma("unroll")                                                          \
        for (int j = 0; j < 4; j++) {                                              \
            int idx = j * THREADS + tid;                                           \
            int r = idx >> 3, s = idx & 7;                                         \
            const float* _p = _gA + (size_t)r * FDIM + s * 8;                      \
            pa0[j] = *(const float4*)_p;                                           \
            pa1[j] = *(const float4*)(_p + 4);                                     \
        }                                                                          \
    } while (0)

#define STSA(ch)                                                                   \
    do {                                                                           \
        uint32_t _dA = sbase + SA_BASE + ((ch) % 3) * SA_SZ;                       \
        _Pragma("unroll")                                                          \
        for (int j = 0; j < 4; j++) {                                              \
            int idx = j * THREADS + tid;                                           \
            int r = idx >> 3, s = idx & 7;                                         \
            uint32_t v0 = h2_bits(__floats2half2_rn(pa0[j].x, pa0[j].y));          \
            uint32_t v1 = h2_bits(__floats2half2_rn(pa0[j].z, pa0[j].w));          \
            uint32_t v2 = h2_bits(__floats2half2_rn(pa1[j].x, pa1[j].y));          \
            uint32_t v3 = h2_bits(__floats2half2_rn(pa1[j].z, pa1[j].w));          \
            uint32_t a = _dA + (r * LDA + s * 8) * 2;                              \
            asm volatile("st.shared.v4.b32 [%0], {%1,%2,%3,%4};"                   \
                         :: "r"(a), "r"(v0), "r"(v1), "r"(v2), "r"(v3)             \
                         : "memory");                                              \
        }                                                                          \
    } while (0)

    float4 pa0[4], pa1[4];

    // ---- prologue: B issued at distance 2 ----
    CPB(0);                                   // group 0
    CPB(1);                                   // group 1
    LDGA(0); STSA(0);
    LDGA(1);
    asm volatile("cp.async.wait_group 1;\n" ::: "memory");   // B(0) landed

    // ---- mainloop: one barrier per chunk; B waits target loads 1 iter old ----
#pragma unroll 1
    for (int ch = 0; ch < NCH; ch++) {
        if (ch + 1 < NCH) STSA(ch + 1);      // A buf (ch+1)%3 free since MMA(ch-2)
        if (ch + 2 < NCH) LDGA(ch + 2);
        __syncthreads();                     // publish A(ch), B(ch); MMA(ch-1) reads done
        if (ch + 2 < NCH) CPB(ch + 2);       // B buf (ch+2)%3 free: MMA(ch-1) done

        const uint32_t sa = sbase + SA_BASE + (ch % 3) * SA_SZ;
        const uint32_t sb = sbase + SB_BASE + (ch % 3) * SB_SZ;
        const int la_row = lane & 15, la_k = (lane >> 4) << 3;

#pragma unroll
        for (int k16 = 0; k16 < KC / 16; k16++) {
            const int k0 = k16 * 16;
            uint32_t a[2][4];
#pragma unroll
            for (int mt = 0; mt < 2; mt++)
                ldsm_x4(a[mt], sa + ((R + mt * 16 + la_row) * LDA + k0 + la_k) * 2);
#pragma unroll
            for (int tp = 0; tp < 4; tp++) {
                uint32_t b[4];
                ldsm_x4t(b, sb + ((k0 + la_row) * LDB + C + tp * 16 + la_k) * 2);
#pragma unroll
                for (int mt = 0; mt < 2; mt++) {
                    mma16816(c[mt][tp * 2],     a[mt], b[0], b[1]);
                    mma16816(c[mt][tp * 2 + 1], a[mt], b[2], b[3]);
                }
            }
        }
        // ensure B(ch+1) landed before next iteration's MMA
        if (ch + 2 < NCH)
            asm volatile("cp.async.wait_group 1;\n" ::: "memory");
        else if (ch + 1 < NCH)
            asm volatile("cp.async.wait_group 0;\n" ::: "memory");
    }

    // ---- epilogue: gate z over this warp's 64 cols ----
    const float* sB1 = smf + B1F / 4;
    const float* sW2 = smf + W2F / 4;
    float zlo[2] = {0.f, 0.f}, zhi[2] = {0.f, 0.f};
#pragma unroll
    for (int mt = 0; mt < 2; mt++) {
#pragma unroll
        for (int ti = 0; ti < 8; ti++) {
            int col0 = C + ti * 8 + 2 * tg;
            float w20 = sW2[col0], w21 = sW2[col0 + 1];
            float b10 = sB1[col0], b11 = sB1[col0 + 1];
            zlo[mt] += fmaxf(c[mt][ti][0] + b10, 0.f) * w20
                     + fmaxf(c[mt][ti][1] + b11, 0.f) * w21;
            zhi[mt] += fmaxf(c[mt][ti][2] + b10, 0.f) * w20
                     + fmaxf(c[mt][ti][3] + b11, 0.f) * w21;
        }
    }
#pragma unroll
    for (int mt = 0; mt < 2; mt++) {
        zlo[mt] += __shfl_xor_sync(0xffffffffu, zlo[mt], 1);
        zlo[mt] += __shfl_xor_sync(0xffffffffu, zlo[mt], 2);
        zhi[mt] += __shfl_xor_sync(0xffffffffu, zhi[mt], 1);
        zhi[mt] += __shfl_xor_sync(0xffffffffu, zhi[mt], 2);
    }
    __syncthreads();   // mainloop smem reads complete before scratch reuse
    const int half = wid >> 2;
    if (tg == 0) {
        float* zp = smf + ZPF / 4 + half * ATOMS;
        zp[R + g]      = zlo[0];
        zp[R + g + 8]  = zhi[0];
        zp[R + g + 16] = zlo[1];
        zp[R + g + 24] = zhi[1];
    }
    __syncthreads();

    if (tid < ATOMS) {
        float z = smf[ZPF / 4 + tid] + smf[ZPF / 4 + ATOMS + tid] + b2[0];
        smf[GTF / 4 + tid] = 1.f / (1.f + expf(-z));
    }
    __syncthreads();

    // ---- phase 2: out[m,f] = sum_n gate[n] * h[m,n,f] (float4, L2 re-read) ----
    const int p = tid >> 7;         // atom parity
    const int q = tid & 127;        // float4 column index
    const float* gate = smf + GTF / 4;
    float4 acc = make_float4(0.f, 0.f, 0.f, 0.f);
    const float* src = hm + q * 4;
#pragma unroll 16
    for (int n = p; n < ATOMS; n += 2) {
        float wv = gate[n];
        float4 v = *(const float4*)(src + (size_t)n * FDIM);
        acc.x = fmaf(wv, v.x, acc.x);
        acc.y = fmaf(wv, v.y, acc.y);
        acc.z = fmaf(wv, v.z, acc.z);
        acc.w = fmaf(wv, v.w, acc.w);
    }
    // combine parities via smem scratch (B region — GEMM done, ordered above)
    float4* red = (float4*)(smem + SB_BASE);
    if (p == 1) red[q] = acc;
    __syncthreads();
    if (p == 0) {
        float4 o = red[q];
        acc.x += o.x; acc.y += o.y; acc.z += o.z; acc.w += o.w;
        *(float4*)(out + (size_t)m * FDIM + q * 4) = acc;
    }

#undef CPB
#undef LDGA
#undef STSA
}

extern "C" void kernel_launch(void* const* d_in, const int* in_sizes, int n_in,
                              void* d_out, int out_size) {
    const float* h  = (const float*)d_in[0];
    const float* W1 = (const float*)d_in[1];
    const float* b1 = (const float*)d_in[2];
    const float* W2 = (const float*)d_in[3];
    const float* b2 = (const float*)d_in[4];
    float* out = (float*)d_out;

    int M = in_sizes[0] / (ATOMS * FDIM);

    format_w1_kernel<<<(FDIM * HID) / (256 * 4), 256>>>(W1);

    cudaFuncSetAttribute(atom_pool_kernel,
                         cudaFuncAttributeMaxDynamicSharedMemorySize, SMEM_BYTES);
    atom_pool_kernel<<<M, THREADS, SMEM_BYTES>>>(h, b1, W2, b2, out);
}

// round 14
// speedup vs baseline: 1.2582x; 1.2582x over previous
#include <cuda_runtime.h>
#include <cuda_fp16.h>
#include <cstdint>

#define ATOMS   128
#define FDIM    512
#define HID     128
#define KC      64
#define NCH     (FDIM / KC)   // 8
#define THREADS 256

#define LDA 72    // halves per A row (64 + 8 pad)
#define LDB 136   // halves per B row (128 + 8 pad)

#define SA_SZ   (ATOMS * LDA * 2)       // 18432
#define SB_SZ   (KC * LDB * 2)          // 17408
#define SA_BASE 0                       // 3 stages
#define SB_BASE (3 * SA_SZ)             // 55296, 2 stages
#define B1F     (SB_BASE + 2 * SB_SZ)   // 90112 (128 f32)
#define W2F     (B1F + 512)             // 90624 (128 f32)
#define ZPF     (W2F + 512)             // 91136 (256 f32)
#define GTF     (ZPF + 1024)            // 92160 (128 f32)
#define SMEM_BYTES (GTF + 512)          // 92672  (x2 CTAs = 185344 -> 2 CTAs/SM)

__device__ __half g_W1h[FDIM * HID];    // W1 fp16, [k][n]

__global__ void format_w1_kernel(const float* __restrict__ W1) {
    int idx = blockIdx.x * blockDim.x + threadIdx.x;   // 16384 float4 slots
    float4 v = ((const float4*)W1)[idx];
    __half2 a = __floats2half2_rn(v.x, v.y);
    __half2 b = __floats2half2_rn(v.z, v.w);
    ((__half2*)g_W1h)[2 * idx]     = a;
    ((__half2*)g_W1h)[2 * idx + 1] = b;
}

__device__ __forceinline__ uint32_t smem_u32(const void* p) {
    uint32_t a;
    asm("{ .reg .u64 t; cvta.to.shared.u64 t, %1; cvt.u32.u64 %0, t; }" : "=r"(a) : "l"(p));
    return a;
}
__device__ __forceinline__ uint32_t h2_bits(__half2 v) {
    uint32_t u; __builtin_memcpy(&u, &v, 4); return u;
}
__device__ __forceinline__ void cp_async16(uint32_t dst, const void* src) {
    asm volatile("cp.async.cg.shared.global [%0], [%1], 16;\n" :: "r"(dst), "l"(src) : "memory");
}
__device__ __forceinline__ void ldsm_x4(uint32_t (&r)[4], uint32_t addr) {
    asm volatile("ldmatrix.sync.aligned.m8n8.x4.shared.b16 {%0,%1,%2,%3}, [%4];"
                 : "=r"(r[0]), "=r"(r[1]), "=r"(r[2]), "=r"(r[3]) : "r"(addr));
}
__device__ __forceinline__ void ldsm_x4t(uint32_t (&r)[4], uint32_t addr) {
    asm volatile("ldmatrix.sync.aligned.m8n8.x4.trans.shared.b16 {%0,%1,%2,%3}, [%4];"
                 : "=r"(r[0]), "=r"(r[1]), "=r"(r[2]), "=r"(r[3]) : "r"(addr));
}
__device__ __forceinline__ void mma16816(float (&d)[4], const uint32_t (&a)[4],
                                         uint32_t b0, uint32_t b1) {
    asm volatile(
        "mma.sync.aligned.m16n8k16.row.col.f32.f16.f16.f32 "
        "{%0,%1,%2,%3}, {%4,%5,%6,%7}, {%8,%9}, {%0,%1,%2,%3};\n"
        : "+f"(d[0]), "+f"(d[1]), "+f"(d[2]), "+f"(d[3])
        : "r"(a[0]), "r"(a[1]), "r"(a[2]), "r"(a[3]), "r"(b0), "r"(b1));
}

__global__ void __launch_bounds__(THREADS, 2)
atom_pool_kernel(const float* __restrict__ h,
                 const float* __restrict__ b1,
                 const float* __restrict__ W2,
                 const float* __restrict__ b2,
                 float* __restrict__ out) {
    extern __shared__ char smem[];
    const uint32_t sbase = smem_u32(smem);
    float* smf = (float*)smem;

    const int m    = blockIdx.x;
    const int tid  = threadIdx.x;
    const int wid  = tid >> 5;
    const int lane = tid & 31;
    const int g    = lane >> 2;
    const int tg   = lane & 3;

    const float* hm = h + (size_t)m * ATOMS * FDIM;

    if (tid < HID) { smf[B1F / 4 + tid] = b1[tid]; smf[W2F / 4 + tid] = W2[tid]; }

    const int R = (wid & 3) * 32;
    const int C = (wid >> 2) * 64;

    float c[2][8][4];
#pragma unroll
    for (int mt = 0; mt < 2; mt++)
#pragma unroll
        for (int ti = 0; ti < 8; ti++)
#pragma unroll
            for (int j = 0; j < 4; j++) c[mt][ti][j] = 0.f;

#define CPB(ch)                                                                    \
    do {                                                                           \
        uint32_t _dB = sbase + SB_BASE + ((ch) & 1) * SB_SZ;                       \
        const __half* _gB = g_W1h + (size_t)(ch) * KC * HID;                       \
        _Pragma("unroll")                                                          \
        for (int j = 0; j < 4; j++) {                                              \
            int idx = j * THREADS + tid;                                           \
            int r = idx >> 4, s = idx & 15;                                        \
            cp_async16(_dB + (r * LDB + s * 8) * 2, _gB + (size_t)r * HID + s * 8);\
        }                                                                          \
        asm volatile("cp.async.commit_group;\n" ::: "memory");                     \
    } while (0)

#define LDGA(ch)                                                                   \
    do {                                                                           \
        const float* _gA = hm + (ch) * KC;                                         \
        _Pragma("unroll")                                                          \
        for (int j = 0; j < 4; j++) {                                              \
            int idx = j * THREADS + tid;                                           \
            int r = idx >> 3, s = idx & 7;                                         \
            const float* _p = _gA + (size_t)r * FDIM + s * 8;                      \
            pa0[j] = *(const float4*)_p;                                           \
            pa1[j] = *(const float4*)(_p + 4);                                     \
        }                                                                          \
    } while (0)

#define STSA(ch)                                                                   \
    do {                                                                           \
        uint32_t _dA = sbase + SA_BASE + ((ch) % 3) * SA_SZ;                       \
        _Pragma("unroll")                                                          \
        for (int j = 0; j < 4; j++) {                                              \
            int idx = j * THREADS + tid;                                           \
            int r = idx >> 3, s = idx & 7;                                         \
            uint32_t v0 = h2_bits(__floats2half2_rn(pa0[j].x, pa0[j].y));          \
            uint32_t v1 = h2_bits(__floats2half2_rn(pa0[j].z, pa0[j].w));          \
            uint32_t v2 = h2_bits(__floats2half2_rn(pa1[j].x, pa1[j].y));          \
            uint32_t v3 = h2_bits(__floats2half2_rn(pa1[j].z, pa1[j].w));          \
            uint32_t a = _dA + (r * LDA + s * 8) * 2;                              \
            asm volatile("st.shared.v4.b32 [%0], {%1,%2,%3,%4};"                   \
                         :: "r"(a), "r"(v0), "r"(v1), "r"(v2), "r"(v3)             \
                         : "memory");                                              \
        }                                                                          \
    } while (0)

    float4 pa0[4], pa1[4];

    // ---- prologue ----
    CPB(0);
    LDGA(0); STSA(0);
    LDGA(1);
    asm volatile("cp.async.wait_group 0;\n" ::: "memory");

    // ---- mainloop: one barrier per chunk ----
#pragma unroll 1
    for (int ch = 0; ch < NCH; ch++) {
        if (ch + 1 < NCH) STSA(ch + 1);      // buf (ch+1)%3 free since MMA(ch-2)
        if (ch + 2 < NCH) LDGA(ch + 2);
        __syncthreads();                     // publish A(ch), B(ch)
        if (ch + 1 < NCH) CPB(ch + 1);       // B buf free: MMA(ch-1) done

        const uint32_t sa = sbase + SA_BASE + (ch % 3) * SA_SZ;
        const uint32_t sb = sbase + SB_BASE + (ch & 1) * SB_SZ;
        const int la_row = lane & 15, la_k = (lane >> 4) << 3;

#pragma unroll
        for (int k16 = 0; k16 < KC / 16; k16++) {
            const int k0 = k16 * 16;
            uint32_t a[2][4];
#pragma unroll
            for (int mt = 0; mt < 2; mt++)
                ldsm_x4(a[mt], sa + ((R + mt * 16 + la_row) * LDA + k0 + la_k) * 2);
#pragma unroll
            for (int tp = 0; tp < 4; tp++) {
                uint32_t b[4];
                ldsm_x4t(b, sb + ((k0 + la_row) * LDB + C + tp * 16 + la_k) * 2);
#pragma unroll
                for (int mt = 0; mt < 2; mt++) {
                    mma16816(c[mt][tp * 2],     a[mt], b[0], b[1]);
                    mma16816(c[mt][tp * 2 + 1], a[mt], b[2], b[3]);
                }
            }
        }
        if (ch + 1 < NCH)
            asm volatile("cp.async.wait_group 0;\n" ::: "memory");
    }

    // ---- epilogue: gate z over this warp's 64 cols ----
    const float* sB1 = smf + B1F / 4;
    const float* sW2 = smf + W2F / 4;
    float zlo[2] = {0.f, 0.f}, zhi[2] = {0.f, 0.f};
#pragma unroll
    for (int mt = 0; mt < 2; mt++) {
#pragma unroll
        for (int ti = 0; ti < 8; ti++) {
            int col0 = C + ti * 8 + 2 * tg;
            float w20 = sW2[col0], w21 = sW2[col0 + 1];
            float b10 = sB1[col0], b11 = sB1[col0 + 1];
            zlo[mt] += fmaxf(c[mt][ti][0] + b10, 0.f) * w20
                     + fmaxf(c[mt][ti][1] + b11, 0.f) * w21;
            zhi[mt] += fmaxf(c[mt][ti][2] + b10, 0.f) * w20
                     + fmaxf(c[mt][ti][3] + b11, 0.f) * w21;
        }
    }
#pragma unroll
    for (int mt = 0; mt < 2; mt++) {
        zlo[mt] += __shfl_xor_sync(0xffffffffu, zlo[mt], 1);
        zlo[mt] += __shfl_xor_sync(0xffffffffu, zlo[mt], 2);
        zhi[mt] += __shfl_xor_sync(0xffffffffu, zhi[mt], 1);
        zhi[mt] += __shfl_xor_sync(0xffffffffu, zhi[mt], 2);
    }
    __syncthreads();   // mainloop smem reads complete before scratch reuse
    const int half = wid >> 2;
    if (tg == 0) {
        float* zp = smf + ZPF / 4 + half * ATOMS;
        zp[R + g]      = zlo[0];
        zp[R + g + 8]  = zhi[0];
        zp[R + g + 16] = zlo[1];
        zp[R + g + 24] = zhi[1];
    }
    __syncthreads();

    if (tid < ATOMS) {
        float z = smf[ZPF / 4 + tid] + smf[ZPF / 4 + ATOMS + tid] + b2[0];
        smf[GTF / 4 + tid] = 1.f / (1.f + expf(-z));
    }
    __syncthreads();

    // ---- phase 2: out[m,f] = sum_n gate[n] * h[m,n,f] (float4, L2 re-read) ----
    const int p = tid >> 7;         // atom parity
    const int q = tid & 127;        // float4 column index
    const float* gate = smf + GTF / 4;
    float4 acc = make_float4(0.f, 0.f, 0.f, 0.f);
    const float* src = hm + q * 4;
#pragma unroll 8
    for (int n = p; n < ATOMS; n += 2) {
        float wv = gate[n];
        float4 v = *(const float4*)(src + (size_t)n * FDIM);
        acc.x = fmaf(wv, v.x, acc.x);
        acc.y = fmaf(wv, v.y, acc.y);
        acc.z = fmaf(wv, v.z, acc.z);
        acc.w = fmaf(wv, v.w, acc.w);
    }
    // combine parities via smem scratch (B region — GEMM done, ordered above)
    float4* red = (float4*)(smem + SB_BASE);
    if (p == 1) red[q] = acc;
    __syncthreads();
    if (p == 0) {
        float4 o = red[q];
        acc.x += o.x; acc.y += o.y; acc.z += o.z; acc.w += o.w;
        *(float4*)(out + (size_t)m * FDIM + q * 4) = acc;
    }

#undef CPB
#undef LDGA
#undef STSA
}

extern "C" void kernel_launch(void* const* d_in, const int* in_sizes, int n_in,
                              void* d_out, int out_size) {
    const float* h  = (const float*)d_in[0];
    const float* W1 = (const float*)d_in[1];
    const float* b1 = (const float*)d_in[2];
    const float* W2 = (const float*)d_in[3];
    const float* b2 = (const float*)d_in[4];
    float* out = (float*)d_out;

    int M = in_sizes[0] / (ATOMS * FDIM);

    format_w1_kernel<<<(FDIM * HID) / (256 * 4), 256>>>(W1);

    cudaFuncSetAttribute(atom_pool_kernel,
                         cudaFuncAttributeMaxDynamicSharedMemorySize, SMEM_BYTES);
    atom_pool_kernel<<<M, THREADS, SMEM_BYTES>>>(h, b1, W2, b2, out);
}